// round 1
// baseline (speedup 1.0000x reference)
#include <cuda_runtime.h>
#include <cstdint>

#define N_LEVELS 12
#define N_FEATURES 2
#define LOG2_T 19
#define T_SIZE (1u << LOG2_T)
#define T_MASK (T_SIZE - 1u)
#define N_PTS 1048576

__constant__ float c_res[N_LEVELS] = {
    16.f, 22.f, 30.f, 42.f, 58.f, 80.f, 110.f, 152.f, 210.f, 290.f, 400.f, 553.f
};

#define P1 2654435761u
#define P2 805459861u

__global__ __launch_bounds__(256) void hashgrid_kernel(
    const float* __restrict__ x,       // (N, 3)
    const float* __restrict__ tables,  // (L, T, 2)
    float* __restrict__ out            // (N, L*2)
) {
    int n = blockIdx.x * blockDim.x + threadIdx.x;
    if (n >= N_PTS) return;

    const float px = x[n * 3 + 0];
    const float py = x[n * 3 + 1];
    const float pz = x[n * 3 + 2];

    float acc[N_LEVELS * 2];

#pragma unroll
    for (int l = 0; l < N_LEVELS; l++) {
        const float res = c_res[l];
        const float sx = px * res;
        const float sy = py * res;
        const float sz = pz * res;
        const float fx = floorf(sx);
        const float fy = floorf(sy);
        const float fz = floorf(sz);
        const float wx = sx - fx;
        const float wy = sy - fy;
        const float wz = sz - fz;

        const uint32_t x0 = (uint32_t)fx;
        const uint32_t y0 = (uint32_t)fy;
        const uint32_t z0 = (uint32_t)fz;

        // hash components: corner = (x0+dx) ^ (y0+dy)*P1 ^ (z0+dz)*P2
        const uint32_t hx0 = x0;
        const uint32_t hx1 = x0 + 1u;
        const uint32_t hy0 = y0 * P1;
        const uint32_t hy1 = hy0 + P1;
        const uint32_t hz0 = z0 * P2;
        const uint32_t hz1 = hz0 + P2;

        const float2* __restrict__ tab =
            reinterpret_cast<const float2*>(tables) + (size_t)l * T_SIZE;

        // 8 independent gathers (MLP=8)
        const float2 f000 = __ldg(&tab[(hx0 ^ hy0 ^ hz0) & T_MASK]);
        const float2 f100 = __ldg(&tab[(hx1 ^ hy0 ^ hz0) & T_MASK]);
        const float2 f010 = __ldg(&tab[(hx0 ^ hy1 ^ hz0) & T_MASK]);
        const float2 f110 = __ldg(&tab[(hx1 ^ hy1 ^ hz0) & T_MASK]);
        const float2 f001 = __ldg(&tab[(hx0 ^ hy0 ^ hz1) & T_MASK]);
        const float2 f101 = __ldg(&tab[(hx1 ^ hy0 ^ hz1) & T_MASK]);
        const float2 f011 = __ldg(&tab[(hx0 ^ hy1 ^ hz1) & T_MASK]);
        const float2 f111 = __ldg(&tab[(hx1 ^ hy1 ^ hz1) & T_MASK]);

        const float ux = 1.f - wx;
        const float uy = 1.f - wy;
        const float uz = 1.f - wz;

        const float w00 = uy * uz;   // (dy=0, dz=0)
        const float w10 = wy * uz;   // (dy=1, dz=0)
        const float w01 = uy * wz;
        const float w11 = wy * wz;

        const float w000 = ux * w00;
        const float w100 = wx * w00;
        const float w010 = ux * w10;
        const float w110 = wx * w10;
        const float w001 = ux * w01;
        const float w101 = wx * w01;
        const float w011 = ux * w11;
        const float w111 = wx * w11;

        float a0 = w000 * f000.x;
        float a1 = w000 * f000.y;
        a0 = fmaf(w100, f100.x, a0);
        a1 = fmaf(w100, f100.y, a1);
        a0 = fmaf(w010, f010.x, a0);
        a1 = fmaf(w010, f010.y, a1);
        a0 = fmaf(w110, f110.x, a0);
        a1 = fmaf(w110, f110.y, a1);
        a0 = fmaf(w001, f001.x, a0);
        a1 = fmaf(w001, f001.y, a1);
        a0 = fmaf(w101, f101.x, a0);
        a1 = fmaf(w101, f101.y, a1);
        a0 = fmaf(w011, f011.x, a0);
        a1 = fmaf(w011, f011.y, a1);
        a0 = fmaf(w111, f111.x, a0);
        a1 = fmaf(w111, f111.y, a1);

        acc[l * 2 + 0] = a0;
        acc[l * 2 + 1] = a1;
    }

    // 24 floats = 6x float4, contiguous per point, warp writes 3KB contiguous
    float4* __restrict__ o4 = reinterpret_cast<float4*>(out + (size_t)n * (N_LEVELS * 2));
#pragma unroll
    for (int i = 0; i < 6; i++) {
        o4[i] = make_float4(acc[i * 4 + 0], acc[i * 4 + 1], acc[i * 4 + 2], acc[i * 4 + 3]);
    }
}

extern "C" void kernel_launch(void* const* d_in, const int* in_sizes, int n_in,
                              void* d_out, int out_size) {
    const float* x = (const float*)d_in[0];       // (N_PTS, 3) float32
    const float* tables = (const float*)d_in[1];  // (12, 2^19, 2) float32
    float* out = (float*)d_out;                   // (N_PTS, 24) float32

    const int threads = 256;
    const int blocks = (N_PTS + threads - 1) / threads;
    hashgrid_kernel<<<blocks, threads>>>(x, tables, out);
}

// round 2
// speedup vs baseline: 1.1695x; 1.1695x over previous
#include <cuda_runtime.h>
#include <cstdint>

#define N_LEVELS 12
#define LOG2_T 19
#define T_SIZE (1u << LOG2_T)
#define T_MASK (T_SIZE - 1u)
#define N_PTS 1048576

#define BIN_BITS 5                    // per dimension
#define BIN_RES (1 << BIN_BITS)      // 32
#define NBINS (1 << (3 * BIN_BITS))  // 32768

#define P1 2654435761u
#define P2 805459861u

__constant__ float c_res[N_LEVELS] = {
    16.f, 22.f, 30.f, 42.f, 58.f, 80.f, 110.f, 152.f, 210.f, 290.f, 400.f, 553.f
};

// Static scratch (no allocation allowed)
__device__ uint32_t g_hist[NBINS];
__device__ uint32_t g_cursor[NBINS];
__device__ float4   g_sx[N_PTS];   // sorted (x,y,z, orig_idx_as_float_bits)

// ---------------------------------------------------------------------------
// 5-bit-per-dim Morton interleave
__device__ __forceinline__ uint32_t expand5(uint32_t v) {
    // v: 5 bits -> spread to every 3rd bit
    v = (v | (v << 8)) & 0x0000F00Fu;
    v = (v | (v << 4)) & 0x000C30C3u;
    v = (v | (v << 2)) & 0x00249249u;
    return v;
}

__device__ __forceinline__ uint32_t bin_id(float px, float py, float pz) {
    uint32_t bx = min((uint32_t)(px * BIN_RES), (uint32_t)(BIN_RES - 1));
    uint32_t by = min((uint32_t)(py * BIN_RES), (uint32_t)(BIN_RES - 1));
    uint32_t bz = min((uint32_t)(pz * BIN_RES), (uint32_t)(BIN_RES - 1));
    return expand5(bx) | (expand5(by) << 1) | (expand5(bz) << 2);
}

// ---------------------------------------------------------------------------
__global__ void zero_hist_kernel() {
    int i = blockIdx.x * blockDim.x + threadIdx.x;
    if (i < NBINS) g_hist[i] = 0u;
}

__global__ __launch_bounds__(256) void hist_kernel(const float* __restrict__ x) {
    int n = blockIdx.x * blockDim.x + threadIdx.x;
    if (n >= N_PTS) return;
    float px = x[n * 3 + 0];
    float py = x[n * 3 + 1];
    float pz = x[n * 3 + 2];
    atomicAdd(&g_hist[bin_id(px, py, pz)], 1u);
}

// Single block, 1024 threads; each thread scans 32 bins sequentially.
__global__ __launch_bounds__(1024) void scan_kernel() {
    __shared__ uint32_t partial[1024];
    int t = threadIdx.x;
    uint32_t sum = 0;
#pragma unroll
    for (int i = 0; i < NBINS / 1024; i++) sum += g_hist[t * (NBINS / 1024) + i];
    partial[t] = sum;
    __syncthreads();
    // Hillis-Steele inclusive scan
    for (int d = 1; d < 1024; d <<= 1) {
        uint32_t v = (t >= d) ? partial[t - d] : 0u;
        __syncthreads();
        partial[t] += v;
        __syncthreads();
    }
    uint32_t running = (t == 0) ? 0u : partial[t - 1];  // exclusive
#pragma unroll
    for (int i = 0; i < NBINS / 1024; i++) {
        int b = t * (NBINS / 1024) + i;
        g_cursor[b] = running;
        running += g_hist[b];
    }
}

__global__ __launch_bounds__(256) void scatter_kernel(const float* __restrict__ x) {
    int n = blockIdx.x * blockDim.x + threadIdx.x;
    if (n >= N_PTS) return;
    float px = x[n * 3 + 0];
    float py = x[n * 3 + 1];
    float pz = x[n * 3 + 2];
    uint32_t b = bin_id(px, py, pz);
    uint32_t pos = atomicAdd(&g_cursor[b], 1u);
    g_sx[pos] = make_float4(px, py, pz, __int_as_float(n));
}

// ---------------------------------------------------------------------------
__global__ __launch_bounds__(256) void hashgrid_kernel(
    const float* __restrict__ tables,  // (L, T, 2)
    float* __restrict__ out            // (N, L*2)
) {
    int j = blockIdx.x * blockDim.x + threadIdx.x;
    if (j >= N_PTS) return;

    const float4 s = g_sx[j];
    const float px = s.x, py = s.y, pz = s.z;
    const int n = __float_as_int(s.w);

    float acc[N_LEVELS * 2];

#pragma unroll
    for (int l = 0; l < N_LEVELS; l++) {
        const float res = c_res[l];
        const float sx = px * res;
        const float sy = py * res;
        const float sz = pz * res;
        const float fx = floorf(sx);
        const float fy = floorf(sy);
        const float fz = floorf(sz);
        const float wx = sx - fx;
        const float wy = sy - fy;
        const float wz = sz - fz;

        const uint32_t x0 = (uint32_t)fx;
        const uint32_t y0 = (uint32_t)fy;
        const uint32_t z0 = (uint32_t)fz;

        const uint32_t hx0 = x0;
        const uint32_t hx1 = x0 + 1u;
        const uint32_t hy0 = y0 * P1;
        const uint32_t hy1 = hy0 + P1;
        const uint32_t hz0 = z0 * P2;
        const uint32_t hz1 = hz0 + P2;

        const float2* __restrict__ tab =
            reinterpret_cast<const float2*>(tables) + (size_t)l * T_SIZE;

        const float2 f000 = __ldg(&tab[(hx0 ^ hy0 ^ hz0) & T_MASK]);
        const float2 f100 = __ldg(&tab[(hx1 ^ hy0 ^ hz0) & T_MASK]);
        const float2 f010 = __ldg(&tab[(hx0 ^ hy1 ^ hz0) & T_MASK]);
        const float2 f110 = __ldg(&tab[(hx1 ^ hy1 ^ hz0) & T_MASK]);
        const float2 f001 = __ldg(&tab[(hx0 ^ hy0 ^ hz1) & T_MASK]);
        const float2 f101 = __ldg(&tab[(hx1 ^ hy0 ^ hz1) & T_MASK]);
        const float2 f011 = __ldg(&tab[(hx0 ^ hy1 ^ hz1) & T_MASK]);
        const float2 f111 = __ldg(&tab[(hx1 ^ hy1 ^ hz1) & T_MASK]);

        const float ux = 1.f - wx;
        const float uy = 1.f - wy;
        const float uz = 1.f - wz;

        const float w00 = uy * uz;
        const float w10 = wy * uz;
        const float w01 = uy * wz;
        const float w11 = wy * wz;

        const float w000 = ux * w00;
        const float w100 = wx * w00;
        const float w010 = ux * w10;
        const float w110 = wx * w10;
        const float w001 = ux * w01;
        const float w101 = wx * w01;
        const float w011 = ux * w11;
        const float w111 = wx * w11;

        float a0 = w000 * f000.x;
        float a1 = w000 * f000.y;
        a0 = fmaf(w100, f100.x, a0);
        a1 = fmaf(w100, f100.y, a1);
        a0 = fmaf(w010, f010.x, a0);
        a1 = fmaf(w010, f010.y, a1);
        a0 = fmaf(w110, f110.x, a0);
        a1 = fmaf(w110, f110.y, a1);
        a0 = fmaf(w001, f001.x, a0);
        a1 = fmaf(w001, f001.y, a1);
        a0 = fmaf(w101, f101.x, a0);
        a1 = fmaf(w101, f101.y, a1);
        a0 = fmaf(w011, f011.x, a0);
        a1 = fmaf(w011, f011.y, a1);
        a0 = fmaf(w111, f111.x, a0);
        a1 = fmaf(w111, f111.y, a1);

        acc[l * 2 + 0] = a0;
        acc[l * 2 + 1] = a1;
    }

    // scatter 24 floats (96 B) to original row n
    float4* __restrict__ o4 = reinterpret_cast<float4*>(out + (size_t)n * (N_LEVELS * 2));
#pragma unroll
    for (int i = 0; i < 6; i++) {
        o4[i] = make_float4(acc[i * 4 + 0], acc[i * 4 + 1], acc[i * 4 + 2], acc[i * 4 + 3]);
    }
}

// ---------------------------------------------------------------------------
extern "C" void kernel_launch(void* const* d_in, const int* in_sizes, int n_in,
                              void* d_out, int out_size) {
    const float* x = (const float*)d_in[0];       // (N_PTS, 3) float32
    const float* tables = (const float*)d_in[1];  // (12, 2^19, 2) float32
    float* out = (float*)d_out;                   // (N_PTS, 24) float32

    const int threads = 256;
    const int blocks = (N_PTS + threads - 1) / threads;

    zero_hist_kernel<<<(NBINS + 255) / 256, 256>>>();
    hist_kernel<<<blocks, threads>>>(x);
    scan_kernel<<<1, 1024>>>();
    scatter_kernel<<<blocks, threads>>>(x);
    hashgrid_kernel<<<blocks, threads>>>(tables, out);
}